// round 2
// baseline (speedup 1.0000x reference)
#include <cuda_runtime.h>
#include <cuda_bf16.h>

// Problem constants
#define BB   512
#define SS   1024
#define FIN  16      // features per (b,s); feature 15 is delta
#define HH   64
#define GG   192     // 3*H
#define NB   4       // batches per CTA
#define NT   192     // threads per CTA (one per output column g)
#define NCTA (BB/NB) // 128

__device__ __forceinline__ float sigmoidf_(float x) {
    return __fdividef(1.0f, 1.0f + __expf(-x));
}
__device__ __forceinline__ float tanhf_(float x) {
    // tanh(x) = 2*sigmoid(2x) - 1, via accurate MUFU.EX2 path
    return __fdividef(2.0f, 1.0f + __expf(-2.0f * x)) - 1.0f;
}

__global__ __launch_bounds__(NT, 1)
void gru_scan_kernel(const float* __restrict__ inputs,   // (B,S,16)
                     const float* __restrict__ k_in,     // (15,192)
                     const float* __restrict__ r_in,     // (64,192)
                     const float* __restrict__ bias,     // (2,192)
                     const float* __restrict__ w1,       // (64,64)
                     const float* __restrict__ b1,       // (64)
                     const float* __restrict__ bn_gamma,
                     const float* __restrict__ bn_beta,
                     const float* __restrict__ bn_mean,
                     const float* __restrict__ bn_var,
                     const float* __restrict__ w2,       // (64,1)
                     const float* __restrict__ b2,       // (1)
                     const float* __restrict__ Tp,       // (1)
                     float* __restrict__ out)            // (B,1)
{
    __shared__ __align__(16) float sm_h[NB][HH];    // hidden state per batch
    __shared__ __align__(16) float sm_x[NB][FIN];   // current-step inputs
    __shared__ __align__(16) float sm_s[NB][256];   // [0:128)=xz+rz,xr+rr ; [128:192)=xh ; [192:256)=rh
    __shared__ float sm_d[NB];

    const int tid = threadIdx.x;
    const int g   = tid;                 // output column 0..191
    const int bbase = blockIdx.x * NB;

    // ---- Load per-column weights into registers (reused for all 1024 steps) ----
    float R[HH];
    #pragma unroll
    for (int k = 0; k < HH; k++) R[k] = r_in[k * GG + g];
    float K[15];
    #pragma unroll
    for (int f = 0; f < 15; f++) K[f] = k_in[f * GG + g];
    const float bi = bias[g];
    const float br = bias[GG + g];

    // init h = 0
    for (int i = tid; i < NB * HH; i += NT) ((float*)sm_h)[i] = 0.0f;
    // preload x for s=0 (16 floats per batch = 4 float4 loads)
    if (tid < NB * 4) {
        int b = tid >> 2, q = tid & 3;
        ((float4*)sm_x[b])[q] =
            *(const float4*)&inputs[(size_t)(bbase + b) * SS * FIN + (size_t)q * 4];
    }
    float dsum = 0.0f;
    __syncthreads();

    for (int s = 0; s < SS; s++) {
        // ---------- Phase A: per-column GEMV (reads sm_h, sm_x) ----------
        float vx[NB], vr[NB];
        #pragma unroll
        for (int b = 0; b < NB; b++) {
            float a0 = 0.f, a1 = 0.f, a2 = 0.f, a3 = 0.f;
            #pragma unroll
            for (int k = 0; k < HH; k += 4) {
                float4 h4 = *(const float4*)&sm_h[b][k];   // warp-broadcast LDS.128
                a0 += h4.x * R[k];
                a1 += h4.y * R[k + 1];
                a2 += h4.z * R[k + 2];
                a3 += h4.w * R[k + 3];
            }
            float x0 = 0.f, x1 = 0.f, x2 = 0.f, x3 = 0.f;
            #pragma unroll
            for (int f = 0; f < 12; f += 4) {
                float4 x4 = *(const float4*)&sm_x[b][f];
                x0 += x4.x * K[f];
                x1 += x4.y * K[f + 1];
                x2 += x4.z * K[f + 2];
                x3 += x4.w * K[f + 3];
            }
            {
                float4 x4 = *(const float4*)&sm_x[b][12];
                x0 += x4.x * K[12];
                x1 += x4.y * K[13];
                x2 += x4.z * K[14];   // feature 15 (delta) excluded
            }
            vr[b] = br + ((a0 + a1) + (a2 + a3));
            vx[b] = bi + ((x0 + x1) + (x2 + x3));
        }
        if (tid < NB) dsum += sm_x[tid][15];   // delta accumulation (free)

        #pragma unroll
        for (int b = 0; b < NB; b++) {
            if (g < 128) {
                sm_s[b][g] = vx[b] + vr[b];        // z-pre and r-pre combined
            } else {
                sm_s[b][g]      = vx[b];           // xh
                sm_s[b][g + 64] = vr[b];           // rh
            }
        }
        __syncthreads();

        // ---------- Phase B: gates (writes sm_h) + prefetch next x (writes sm_x) ----------
        if (s + 1 < SS && tid < NB * 4) {
            int b = tid >> 2, q = tid & 3;
            ((float4*)sm_x[b])[q] =
                *(const float4*)&inputs[(size_t)(bbase + b) * SS * FIN +
                                        (size_t)(s + 1) * FIN + (size_t)q * 4];
        }
        for (int i = tid; i < NB * HH; i += NT) {
            int b = i >> 6, j = i & 63;
            float z  = sigmoidf_(sm_s[b][j]);
            float r  = sigmoidf_(sm_s[b][64 + j]);
            float hh = tanhf_(sm_s[b][128 + j] + r * sm_s[b][192 + j]);
            float ho = sm_h[b][j];
            sm_h[b][j] = z * ho + (1.0f - z) * hh;
        }
        __syncthreads();
    }

    // ---------- Epilogue: delta effect + MLP head + BN ----------
    if (tid < NB) sm_d[tid] = Tp[0] * dsum * (1.0f / (float)SS);
    __syncthreads();

    for (int i = tid; i < NB * HH; i += NT) {
        int b = i >> 6, j = i & 63;
        float db  = sm_d[b];
        float acc = b1[j];
        #pragma unroll 8
        for (int k = 0; k < HH; k++)
            acc += (sm_h[b][k] + db) * w1[k * HH + j];
        float hr = fmaxf(acc, 0.0f);
        float hb = (hr - bn_mean[j]) * rsqrtf(bn_var[j] + 1e-3f) * bn_gamma[j] + bn_beta[j];
        sm_s[b][j] = hb * w2[j];
    }
    __syncthreads();

    if (tid < NB) {
        float acc = b2[0];
        #pragma unroll 8
        for (int j = 0; j < HH; j++) acc += sm_s[tid][j];
        out[bbase + tid] = acc;
    }
}

extern "C" void kernel_launch(void* const* d_in, const int* in_sizes, int n_in,
                              void* d_out, int out_size) {
    const float* inputs   = (const float*)d_in[0];
    const float* gk       = (const float*)d_in[1];
    const float* grk      = (const float*)d_in[2];
    const float* gbias    = (const float*)d_in[3];
    const float* w1       = (const float*)d_in[4];
    const float* b1       = (const float*)d_in[5];
    const float* bn_gamma = (const float*)d_in[6];
    const float* bn_beta  = (const float*)d_in[7];
    const float* bn_mean  = (const float*)d_in[8];
    const float* bn_var   = (const float*)d_in[9];
    const float* w2       = (const float*)d_in[10];
    const float* b2       = (const float*)d_in[11];
    const float* T        = (const float*)d_in[12];
    float* out = (float*)d_out;

    gru_scan_kernel<<<NCTA, NT>>>(inputs, gk, grk, gbias, w1, b1,
                                  bn_gamma, bn_beta, bn_mean, bn_var,
                                  w2, b2, T, out);
}

// round 3
// speedup vs baseline: 1.2256x; 1.2256x over previous
#include <cuda_runtime.h>
#include <cuda_bf16.h>

// Problem constants
#define BB   512
#define SS   1024
#define FIN  16      // features per (b,s); feature 15 is delta
#define HH   64
#define GG   192     // 3*H
#define NB   4       // batches per CTA
#define NT   384     // 12 warps: threads (g, pair) ; pair handles 2 batches
#define NCTA (BB/NB) // 128

typedef unsigned long long u64;

// ---- packed f32x2 helpers (bit-exact fp32, 2 FMA per fma-pipe slot) ----
__device__ __forceinline__ u64 pack2(float lo, float hi) {
    u64 r; asm("mov.b64 %0, {%1, %2};" : "=l"(r) : "f"(lo), "f"(hi)); return r;
}
__device__ __forceinline__ void unpack2(u64 v, float& lo, float& hi) {
    asm("mov.b64 {%0, %1}, %2;" : "=f"(lo), "=f"(hi) : "l"(v));
}
__device__ __forceinline__ u64 fma2(u64 a, u64 b, u64 c) {
    u64 d; asm("fma.rn.f32x2 %0, %1, %2, %3;" : "=l"(d) : "l"(a), "l"(b), "l"(c)); return d;
}
__device__ __forceinline__ u64 add2(u64 a, u64 b) {
    u64 d; asm("add.rn.f32x2 %0, %1, %2;" : "=l"(d) : "l"(a), "l"(b)); return d;
}

__device__ __forceinline__ float sigmoidf_(float x) {
    return __fdividef(1.0f, 1.0f + __expf(-x));
}
__device__ __forceinline__ float tanhf_(float x) {
    return __fdividef(2.0f, 1.0f + __expf(-2.0f * x)) - 1.0f;
}

__global__ __launch_bounds__(NT, 1)
void gru_scan_kernel(const float* __restrict__ inputs,   // (B,S,16)
                     const float* __restrict__ k_in,     // (15,192)
                     const float* __restrict__ r_in,     // (64,192)
                     const float* __restrict__ bias,     // (2,192)
                     const float* __restrict__ w1,       // (64,64)
                     const float* __restrict__ b1,       // (64)
                     const float* __restrict__ bn_gamma,
                     const float* __restrict__ bn_beta,
                     const float* __restrict__ bn_mean,
                     const float* __restrict__ bn_var,
                     const float* __restrict__ w2,       // (64,1)
                     const float* __restrict__ b2,       // (1)
                     const float* __restrict__ Tp,       // (1)
                     float* __restrict__ out)            // (B,1)
{
    __shared__ __align__(16) float sm_h[NB][HH];    // hidden state per batch
    __shared__ __align__(16) float sm_x[NB][FIN];   // current-step inputs
    __shared__ __align__(16) float sm_s[NB][256];   // [0:64)=z-pre [64:128)=r-pre [128:192)=xh [192:256)=rh
    __shared__ float sm_d[NB];

    const int tid   = threadIdx.x;
    const int g     = tid % GG;          // output column 0..191
    const int pr    = tid / GG;          // 0 -> batches 0,1 ; 1 -> batches 2,3
    const int b0    = pr * 2;
    const int bbase = blockIdx.x * NB;

    // ---- Per-column weights in registers, packed as f32x2 pairs over k ----
    u64 R2[32];
    #pragma unroll
    for (int k2 = 0; k2 < 32; k2++)
        R2[k2] = pack2(r_in[(2 * k2) * GG + g], r_in[(2 * k2 + 1) * GG + g]);
    u64 K2[8];
    #pragma unroll
    for (int f2 = 0; f2 < 8; f2++) {
        float lo = k_in[(2 * f2) * GG + g];
        float hi = (2 * f2 + 1 < 15) ? k_in[(2 * f2 + 1) * GG + g] : 0.0f; // lane 15 (delta) masked
        K2[f2] = pack2(lo, hi);
    }
    const float bi = bias[g];
    const float br = bias[GG + g];

    // init h = 0
    for (int i = tid; i < NB * HH; i += NT) ((float*)sm_h)[i] = 0.0f;
    // preload x for s=0
    if (tid < NB * 4) {
        int b = tid >> 2, q = tid & 3;
        ((float4*)sm_x[b])[q] =
            *(const float4*)&inputs[(size_t)(bbase + b) * SS * FIN + (size_t)q * 4];
    }
    float dsum = 0.0f;
    __syncthreads();

    for (int s = 0; s < SS; s++) {
        // ---------- Phase A: per-column GEMV via f32x2 ----------
        float vx[2], vr[2];
        #pragma unroll
        for (int u = 0; u < 2; u++) {
            const int b = b0 + u;
            const ulonglong2* h4 = (const ulonglong2*)sm_h[b];  // LDS.128 broadcasts
            u64 a0 = 0ull, a1 = 0ull, a2 = 0ull, a3 = 0ull;
            #pragma unroll
            for (int q = 0; q < 16; q += 2) {
                ulonglong2 hv0 = h4[q];
                ulonglong2 hv1 = h4[q + 1];
                a0 = fma2(hv0.x, R2[2 * q],     a0);
                a1 = fma2(hv0.y, R2[2 * q + 1], a1);
                a2 = fma2(hv1.x, R2[2 * q + 2], a2);
                a3 = fma2(hv1.y, R2[2 * q + 3], a3);
            }
            const ulonglong2* x4 = (const ulonglong2*)sm_x[b];
            u64 c0 = 0ull, c1 = 0ull;
            #pragma unroll
            for (int q = 0; q < 4; q += 2) {
                ulonglong2 xv0 = x4[q];
                ulonglong2 xv1 = x4[q + 1];
                c0 = fma2(xv0.x, K2[2 * q],     c0);
                c1 = fma2(xv0.y, K2[2 * q + 1], c1);
                c0 = fma2(xv1.x, K2[2 * q + 2], c0);
                c1 = fma2(xv1.y, K2[2 * q + 3], c1);
            }
            u64 ar = add2(add2(a0, a1), add2(a2, a3));
            float r0, r1; unpack2(ar, r0, r1);
            vr[u] = br + (r0 + r1);
            u64 cx = add2(c0, c1);
            float x0, x1; unpack2(cx, x0, x1);
            vx[u] = bi + (x0 + x1);
        }
        if (tid < NB) dsum += sm_x[tid][15];   // delta accumulation (free)

        #pragma unroll
        for (int u = 0; u < 2; u++) {
            const int b = b0 + u;
            if (g < 128) {
                sm_s[b][g] = vx[u] + vr[u];        // z-pre / r-pre combined
            } else {
                sm_s[b][g]      = vx[u];           // xh
                sm_s[b][g + 64] = vr[u];           // rh
            }
        }
        __syncthreads();

        // ---------- Phase B: gates + prefetch next x ----------
        if (s + 1 < SS && tid < NB * 4) {
            int b = tid >> 2, q = tid & 3;
            ((float4*)sm_x[b])[q] =
                *(const float4*)&inputs[(size_t)(bbase + b) * SS * FIN +
                                        (size_t)(s + 1) * FIN + (size_t)q * 4];
        }
        if (tid < NB * HH) {
            int b = tid >> 6, j = tid & 63;
            float z  = sigmoidf_(sm_s[b][j]);
            float r  = sigmoidf_(sm_s[b][64 + j]);
            float hh = tanhf_(sm_s[b][128 + j] + r * sm_s[b][192 + j]);
            float ho = sm_h[b][j];
            sm_h[b][j] = z * ho + (1.0f - z) * hh;
        }
        __syncthreads();
    }

    // ---------- Epilogue: delta effect + MLP head + BN ----------
    if (tid < NB) sm_d[tid] = Tp[0] * dsum * (1.0f / (float)SS);
    __syncthreads();

    if (tid < NB * HH) {
        int b = tid >> 6, j = tid & 63;
        float db  = sm_d[b];
        float acc = b1[j];
        #pragma unroll 8
        for (int k = 0; k < HH; k++)
            acc += (sm_h[b][k] + db) * w1[k * HH + j];
        float hr = fmaxf(acc, 0.0f);
        float hb = (hr - bn_mean[j]) * rsqrtf(bn_var[j] + 1e-3f) * bn_gamma[j] + bn_beta[j];
        sm_s[b][j] = hb * w2[j];
    }
    __syncthreads();

    if (tid < NB) {
        float acc = b2[0];
        #pragma unroll 8
        for (int j = 0; j < HH; j++) acc += sm_s[tid][j];
        out[bbase + tid] = acc;
    }
}

extern "C" void kernel_launch(void* const* d_in, const int* in_sizes, int n_in,
                              void* d_out, int out_size) {
    const float* inputs   = (const float*)d_in[0];
    const float* gk       = (const float*)d_in[1];
    const float* grk      = (const float*)d_in[2];
    const float* gbias    = (const float*)d_in[3];
    const float* w1       = (const float*)d_in[4];
    const float* b1       = (const float*)d_in[5];
    const float* bn_gamma = (const float*)d_in[6];
    const float* bn_beta  = (const float*)d_in[7];
    const float* bn_mean  = (const float*)d_in[8];
    const float* bn_var   = (const float*)d_in[9];
    const float* w2       = (const float*)d_in[10];
    const float* b2       = (const float*)d_in[11];
    const float* T        = (const float*)d_in[12];
    float* out = (float*)d_out;

    gru_scan_kernel<<<NCTA, NT>>>(inputs, gk, grk, gbias, w1, b1,
                                  bn_gamma, bn_beta, bn_mean, bn_var,
                                  w2, b2, T, out);
}